// round 1
// baseline (speedup 1.0000x reference)
#include <cuda_runtime.h>

// Problem dims
#define BSZ 256
#define HID 4096
#define NIN 1024
#define NOUT 10
#define STEPS_TOTAL 25
#define STEPS_FREE 20

// Persistent device scratch (no allocation allowed in kernel_launch)
__device__ float g_rx[BSZ * NIN];
__device__ float g_c0[BSZ * HID];
__device__ float g_s1[2][BSZ * HID];
__device__ float g_s2[2][BSZ * HID];
__device__ float g_s3[2][BSZ * NOUT];

__global__ void clip_kernel(const float* __restrict__ x, float* __restrict__ rx, int n) {
    int i = blockIdx.x * blockDim.x + threadIdx.x;
    if (i < n) rx[i] = fminf(fmaxf(x[i], 0.0f), 1.0f);
}

__global__ void zero_kernel(float* __restrict__ p, int n) {
    int i = blockIdx.x * blockDim.x + threadIdx.x;
    if (i < n) p[i] = 0.0f;
}

// SGEMM: C = A[M,K] @ B[K,N], tiles BM=128, BN=64, BK=16, 256 threads,
// per-thread 8x4 micro-tile. Dims must divide tile sizes (they do here).
// MODE 0: Cout = acc                       (plain store, used for c0)
// MODE 1: Cout = clip(0.5*Sold + 0.25*C0 + 0.25*acc)            (s1 update)
// MODE 2: acc += s3old @ bw2 (K=10 fold-in);
//         Cout = clip(0.5*Sold + 0.25*acc)                      (s2 update)
#define BM 128
#define BN 64
#define BK 16

template <int MODE>
__global__ __launch_bounds__(256) void sgemm_kernel(
    const float* __restrict__ A, const float* __restrict__ Bm,
    int K, int N,
    float* __restrict__ Cout,
    const float* __restrict__ Sold, const float* __restrict__ C0,
    const float* __restrict__ s3old, const float* __restrict__ bw2)
{
    __shared__ float As[BK][BM];
    __shared__ float Bs[BK][BN];

    const int tid = threadIdx.x;
    const int tx = tid & 15;        // 0..15 -> col groups of 4
    const int ty = tid >> 4;        // 0..15 -> row groups of 8
    const int rowBase = blockIdx.y * BM;
    const int colBase = blockIdx.x * BN;

    float acc[8][4];
#pragma unroll
    for (int i = 0; i < 8; i++)
#pragma unroll
        for (int j = 0; j < 4; j++) acc[i][j] = 0.0f;

    for (int kt = 0; kt < K; kt += BK) {
        // Load A tile [128 x 16] as 512 float4 (2 per thread), store transposed
#pragma unroll
        for (int u = 0; u < 2; u++) {
            int q = tid + u * 256;
            int r = q >> 2;
            int c = (q & 3) * 4;
            float4 v = *(const float4*)(A + (size_t)(rowBase + r) * K + kt + c);
            As[c + 0][r] = v.x;
            As[c + 1][r] = v.y;
            As[c + 2][r] = v.z;
            As[c + 3][r] = v.w;
        }
        // Load B tile [16 x 64] as 256 float4 (1 per thread)
        {
            int r = tid >> 4;
            int c = (tid & 15) * 4;
            float4 v = *(const float4*)(Bm + (size_t)(kt + r) * N + colBase + c);
            *(float4*)&Bs[r][c] = v;
        }
        __syncthreads();

#pragma unroll
        for (int kk = 0; kk < BK; kk++) {
            float a[8], b[4];
#pragma unroll
            for (int i = 0; i < 8; i++) a[i] = As[kk][ty * 8 + i];
#pragma unroll
            for (int j = 0; j < 4; j++) b[j] = Bs[kk][tx * 4 + j];
#pragma unroll
            for (int i = 0; i < 8; i++)
#pragma unroll
                for (int j = 0; j < 4; j++)
                    acc[i][j] = fmaf(a[i], b[j], acc[i][j]);
        }
        __syncthreads();
    }

    if (MODE == 2) {
        // Fold in the tiny s3 @ bw2 term (K = 10)
#pragma unroll
        for (int k = 0; k < NOUT; k++) {
            float bv[4];
#pragma unroll
            for (int j = 0; j < 4; j++)
                bv[j] = bw2[(size_t)k * N + colBase + tx * 4 + j];
#pragma unroll
            for (int i = 0; i < 8; i++) {
                float av = s3old[(rowBase + ty * 8 + i) * NOUT + k];
#pragma unroll
                for (int j = 0; j < 4; j++)
                    acc[i][j] = fmaf(av, bv[j], acc[i][j]);
            }
        }
    }

#pragma unroll
    for (int i = 0; i < 8; i++) {
        int row = rowBase + ty * 8 + i;
#pragma unroll
        for (int j = 0; j < 4; j++) {
            int col = colBase + tx * 4 + j;
            size_t idx = (size_t)row * N + col;
            float v;
            if (MODE == 0) {
                v = acc[i][j];
            } else if (MODE == 1) {
                v = 0.5f * Sold[idx] + 0.25f * C0[idx] + 0.25f * acc[i][j];
                v = fminf(fmaxf(v, 0.0f), 1.0f);
            } else {
                v = 0.5f * Sold[idx] + 0.25f * acc[i][j];
                v = fminf(fmaxf(v, 0.0f), 1.0f);
            }
            Cout[idx] = v;
        }
    }
}

// p3 = s2 @ fw2 ([256,4096]@[4096,10]); then s3 update.
// free:  s3' = clip(0.5*(s3 + p3))
// weak:  s3' = clip(0.5*(p3 + y))        (EPS=0.5, BETA=0.5 collapse)
__global__ __launch_bounds__(256) void s3_kernel(
    const float* __restrict__ s2, const float* __restrict__ fw2,
    const float* __restrict__ s3old, const float* __restrict__ y,
    float* __restrict__ s3new, int weak)
{
    int row = blockIdx.x;
    int tid = threadIdx.x;
    const float* s2r = s2 + (size_t)row * HID;

    float acc[NOUT];
#pragma unroll
    for (int j = 0; j < NOUT; j++) acc[j] = 0.0f;

    for (int k = tid; k < HID; k += 256) {
        float sv = s2r[k];
#pragma unroll
        for (int j = 0; j < NOUT; j++)
            acc[j] = fmaf(sv, fw2[(size_t)k * NOUT + j], acc[j]);
    }

    __shared__ float partial[8][NOUT];
#pragma unroll
    for (int j = 0; j < NOUT; j++) {
        float v = acc[j];
#pragma unroll
        for (int o = 16; o > 0; o >>= 1)
            v += __shfl_down_sync(0xffffffffu, v, o);
        if ((tid & 31) == 0) partial[tid >> 5][j] = v;
    }
    __syncthreads();

    if (tid < NOUT) {
        float p3 = 0.0f;
#pragma unroll
        for (int w = 0; w < 8; w++) p3 += partial[w][tid];
        float v;
        if (weak) {
            v = 0.5f * (p3 + y[row * NOUT + tid]);
        } else {
            v = 0.5f * (s3old[row * NOUT + tid] + p3);
        }
        s3new[row * NOUT + tid] = fminf(fmaxf(v, 0.0f), 1.0f);
    }
}

__global__ void concat_kernel(const float* __restrict__ s1,
                              const float* __restrict__ s2,
                              const float* __restrict__ s3,
                              float* __restrict__ out)
{
    int i = blockIdx.x * blockDim.x + threadIdx.x;
    const int W = HID + HID + NOUT;  // 8202
    if (i >= BSZ * W) return;
    int row = i / W;
    int c = i - row * W;
    float v;
    if (c < HID)            v = s1[(size_t)row * HID + c];
    else if (c < 2 * HID)   v = s2[(size_t)row * HID + (c - HID)];
    else                    v = s3[row * NOUT + (c - 2 * HID)];
    out[i] = v;
}

extern "C" void kernel_launch(void* const* d_in, const int* in_sizes, int n_in,
                              void* d_out, int out_size)
{
    const float* x   = (const float*)d_in[0];
    const float* fw0 = (const float*)d_in[1];
    const float* fw1 = (const float*)d_in[2];
    const float* fw2 = (const float*)d_in[3];
    // d_in[4] = bw0 (unused by the dynamics)
    const float* bw1 = (const float*)d_in[5];
    const float* bw2 = (const float*)d_in[6];
    const float* y   = (const float*)d_in[7];
    float* out = (float*)d_out;

    float *rx, *c0, *s1base, *s2base, *s3base;
    cudaGetSymbolAddress((void**)&rx, g_rx);
    cudaGetSymbolAddress((void**)&c0, g_c0);
    cudaGetSymbolAddress((void**)&s1base, g_s1);
    cudaGetSymbolAddress((void**)&s2base, g_s2);
    cudaGetSymbolAddress((void**)&s3base, g_s3);

    float* s1p[2] = { s1base, s1base + (size_t)BSZ * HID };
    float* s2p[2] = { s2base, s2base + (size_t)BSZ * HID };
    float* s3p[2] = { s3base, s3base + (size_t)BSZ * NOUT };

    // rx = clip(x, 0, 1)
    clip_kernel<<<(BSZ * NIN + 255) / 256, 256>>>(x, rx, BSZ * NIN);

    // c0 = rx @ fw0   (loop-invariant)
    dim3 grid_c0(HID / BN, BSZ / BM);
    sgemm_kernel<0><<<grid_c0, 256>>>(rx, fw0, NIN, HID, c0,
                                      nullptr, nullptr, nullptr, nullptr);

    // zero initial states (buffer 0)
    zero_kernel<<<(BSZ * HID + 255) / 256, 256>>>(s1p[0], BSZ * HID);
    zero_kernel<<<(BSZ * HID + 255) / 256, 256>>>(s2p[0], BSZ * HID);
    zero_kernel<<<(BSZ * NOUT + 255) / 256, 256>>>(s3p[0], BSZ * NOUT);

    dim3 grid(HID / BN, BSZ / BM);  // 64 x 2 = 128 blocks
    for (int t = 0; t < STEPS_TOTAL; t++) {
        int p = t & 1;
        int q = 1 - p;
        int weak = (t >= STEPS_FREE) ? 1 : 0;

        // s1' = clip(0.5*s1 + 0.25*c0 + 0.25*(s2 @ bw1))
        sgemm_kernel<1><<<grid, 256>>>(s2p[p], bw1, HID, HID, s1p[q],
                                       s1p[p], c0, nullptr, nullptr);
        // s2' = clip(0.5*s2 + 0.25*(s1 @ fw1 + s3 @ bw2))
        sgemm_kernel<2><<<grid, 256>>>(s1p[p], fw1, HID, HID, s2p[q],
                                       s2p[p], nullptr, s3p[p], bw2);
        // s3 update
        s3_kernel<<<BSZ, 256>>>(s2p[p], fw2, s3p[p], y, s3p[q], weak);
    }

    // Final states live in buffer index 25 & 1 == 1
    int fin = STEPS_TOTAL & 1;
    concat_kernel<<<(BSZ * (2 * HID + NOUT) + 255) / 256, 256>>>(
        s1p[fin], s2p[fin], s3p[fin], out);
}

// round 3
// speedup vs baseline: 3.8528x; 3.8528x over previous
#include <cuda_runtime.h>
#include <cstdint>

#define BSZ 256
#define HID 4096
#define NIN 1024
#define NOUT 10
#define STEPS_TOTAL 25
#define STEPS_FREE 20

// GEMM tiling
#define BM 128
#define BN 128
#define BK 32
#define NSTAGE 3
#define PAD 36                          // smem row stride (floats); 36%32=4 -> conflict-free frags
#define STAGE_FLOATS (2 * 128 * PAD)    // A + B tiles = 9216 floats
#define SMEM_BYTES (NSTAGE * STAGE_FLOATS * 4)  // 110592 B

// ---------------- persistent device scratch ----------------
__device__ __align__(128) float g_rx[BSZ * NIN];
__device__ __align__(128) float g_c0[BSZ * HID];
__device__ __align__(128) float g_s1[2][BSZ * HID];
__device__ __align__(128) float g_s2[2][BSZ * HID];
__device__ __align__(128) float g_s3[2][BSZ * NOUT];
__device__ __align__(128) float g_fw0T[(size_t)HID * NIN];
__device__ __align__(128) float g_fw1T[(size_t)HID * HID];
__device__ __align__(128) float g_bw1T[(size_t)HID * HID];

// ---------------- helpers ----------------
__device__ __forceinline__ float tf32_rna(float x) {
    uint32_t u;
    asm("cvt.rna.tf32.f32 %0, %1;" : "=r"(u) : "f"(x));
    return __uint_as_float(u);
}

__device__ __forceinline__ uint32_t smem_u32(const void* p) {
    uint32_t a;
    asm("{ .reg .u64 t; cvta.to.shared.u64 t, %1; cvt.u32.u64 %0, t; }"
        : "=r"(a) : "l"(p));
    return a;
}

__device__ __forceinline__ void cp16(uint32_t dst, const void* src) {
    asm volatile("cp.async.cg.shared.global [%0], [%1], 16;"
                 :: "r"(dst), "l"(src) : "memory");
}
#define CP_COMMIT() asm volatile("cp.async.commit_group;" ::: "memory")
#define CP_WAIT(n)  asm volatile("cp.async.wait_group %0;" :: "n"(n) : "memory")

// m16n8k8 tf32 mma: D += A*B, row.col, f32 accum
__device__ __forceinline__ void mma_tf32(float* c, const uint32_t* a,
                                         uint32_t b0, uint32_t b1) {
    asm volatile(
        "mma.sync.aligned.m16n8k8.row.col.f32.tf32.tf32.f32 "
        "{%0,%1,%2,%3}, {%4,%5,%6,%7}, {%8,%9}, {%0,%1,%2,%3};"
        : "+f"(c[0]), "+f"(c[1]), "+f"(c[2]), "+f"(c[3])
        : "r"(a[0]), "r"(a[1]), "r"(a[2]), "r"(a[3]), "r"(b0), "r"(b1));
}

// ---------------- GEMM tile (device) ----------------
// Out tile [128,128] at (rowBase,colBase) of D[M,4096] = A[M,K] @ BT[4096,K]^T
// mode 0: Out = acc                               (c0)
// mode 1: Out = tf32(clip(0.5*Sold + 0.25*C0p + 0.25*acc))      (s1 update)
// mode 2: Out = tf32(clip(0.5*Sold + 0.25*(acc + s3old@bw2)))   (s2 update)
__device__ __forceinline__ void gemm_tile(
    const float* __restrict__ A, const float* __restrict__ BT, int K,
    float* __restrict__ Out,
    const float* __restrict__ Sold, const float* __restrict__ C0p,
    const float* __restrict__ s3old, const float* __restrict__ bw2,
    int mode, int rowBase, int colBase, float* smem)
{
    const int tid  = threadIdx.x;
    const int lane = tid & 31;
    const int wid  = tid >> 5;
    const int g = lane >> 2, q = lane & 3;
    const int warpM = wid & 3;   // 4 row-groups of 32
    const int warpN = wid >> 2;  // 2 col-groups of 64

    float acc[2][8][4];
#pragma unroll
    for (int mi = 0; mi < 2; mi++)
#pragma unroll
        for (int ni = 0; ni < 8; ni++)
#pragma unroll
            for (int t = 0; t < 4; t++) acc[mi][ni][t] = 0.0f;

    const int ldr  = tid >> 1;           // 0..127
    const int seg0 = (tid & 1) * 4;      // 0 or 4

    const float* Ag = A  + (size_t)(rowBase + ldr) * K;
    const float* Bg = BT + (size_t)(colBase + ldr) * K;

    const int nIt = K / BK;

#define LOAD_STAGE(s, kt)                                            \
    do {                                                             \
        float* As_ = smem + (s) * STAGE_FLOATS;                      \
        float* Bs_ = As_ + 128 * PAD;                                \
        uint32_t dA = smem_u32(As_ + ldr * PAD);                     \
        uint32_t dB = smem_u32(Bs_ + ldr * PAD);                     \
        _Pragma("unroll")                                            \
        for (int u = 0; u < 4; u++) {                                \
            int sg = seg0 + u;                                       \
            cp16(dA + sg * 16, Ag + (kt) + sg * 4);                  \
            cp16(dB + sg * 16, Bg + (kt) + sg * 4);                  \
        }                                                            \
    } while (0)

    LOAD_STAGE(0, 0);  CP_COMMIT();
    LOAD_STAGE(1, BK); CP_COMMIT();

    for (int it = 0; it < nIt; ++it) {
        CP_WAIT(1);
        __syncthreads();
        if (it + 2 < nIt) {
            int s2i = (it + 2) % NSTAGE;
            LOAD_STAGE(s2i, (it + 2) * BK);
        }
        CP_COMMIT();

        const float* As = smem + (it % NSTAGE) * STAGE_FLOATS;
        const float* Bs = As + 128 * PAD;
        const float* aB = As + (warpM * 32 + g) * PAD + q;
        const float* bB = Bs + (warpN * 64 + g) * PAD + q;

#pragma unroll
        for (int kk = 0; kk < 4; kk++) {
            const int ko = kk * 8;
            uint32_t a[2][4];
#pragma unroll
            for (int mi = 0; mi < 2; mi++) {
                a[mi][0] = __float_as_uint(aB[(mi * 16 + 0) * PAD + ko]);
                a[mi][1] = __float_as_uint(aB[(mi * 16 + 8) * PAD + ko]);
                a[mi][2] = __float_as_uint(aB[(mi * 16 + 0) * PAD + ko + 4]);
                a[mi][3] = __float_as_uint(aB[(mi * 16 + 8) * PAD + ko + 4]);
            }
#pragma unroll
            for (int ni = 0; ni < 8; ni++) {
                uint32_t b0 = __float_as_uint(bB[ni * 8 * PAD + ko]);
                uint32_t b1 = __float_as_uint(bB[ni * 8 * PAD + ko + 4]);
                mma_tf32(acc[0][ni], a[0], b0, b1);
                mma_tf32(acc[1][ni], a[1], b0, b1);
            }
        }
    }
#undef LOAD_STAGE

    // ---------------- epilogue ----------------
    const int rw = rowBase + warpM * 32;
    const int cw = colBase + warpN * 64;

    if (mode == 2) {
        // fold in s3old @ bw2 (K = 10), pure fp32
        float s3r[2][2][10];
#pragma unroll
        for (int mi = 0; mi < 2; mi++)
#pragma unroll
            for (int h = 0; h < 2; h++) {
                const int r = rw + mi * 16 + h * 8 + g;
#pragma unroll
                for (int k = 0; k < NOUT; k++)
                    s3r[mi][h][k] = s3old[r * NOUT + k];
            }
#pragma unroll
        for (int ni = 0; ni < 8; ni++) {
            const int cb = cw + ni * 8 + q * 2;
#pragma unroll
            for (int k = 0; k < NOUT; k++) {
                const float2 b2 = *(const float2*)&bw2[(size_t)k * HID + cb];
#pragma unroll
                for (int mi = 0; mi < 2; mi++) {
                    acc[mi][ni][0] = fmaf(s3r[mi][0][k], b2.x, acc[mi][ni][0]);
                    acc[mi][ni][1] = fmaf(s3r[mi][0][k], b2.y, acc[mi][ni][1]);
                    acc[mi][ni][2] = fmaf(s3r[mi][1][k], b2.x, acc[mi][ni][2]);
                    acc[mi][ni][3] = fmaf(s3r[mi][1][k], b2.y, acc[mi][ni][3]);
                }
            }
        }
    }

#pragma unroll
    for (int mi = 0; mi < 2; mi++) {
#pragma unroll
        for (int ni = 0; ni < 8; ni++) {
            const int r0 = rw + mi * 16 + g;
            const int cb = cw + ni * 8 + q * 2;
#pragma unroll
            for (int h = 0; h < 2; h++) {
                const size_t idx = (size_t)(r0 + h * 8) * HID + cb;
                float vx = acc[mi][ni][h * 2 + 0];
                float vy = acc[mi][ni][h * 2 + 1];
                float2 o;
                if (mode == 0) {
                    o.x = vx; o.y = vy;
                } else {
                    const float2 so = *(const float2*)&Sold[idx];
                    if (mode == 1) {
                        const float2 c2 = *(const float2*)&C0p[idx];
                        vx = 0.5f * so.x + 0.25f * c2.x + 0.25f * vx;
                        vy = 0.5f * so.y + 0.25f * c2.y + 0.25f * vy;
                    } else {
                        vx = 0.5f * so.x + 0.25f * vx;
                        vy = 0.5f * so.y + 0.25f * vy;
                    }
                    vx = fminf(fmaxf(vx, 0.0f), 1.0f);
                    vy = fminf(fmaxf(vy, 0.0f), 1.0f);
                    o.x = tf32_rna(vx);   // states feed next-step mma: keep exact tf32
                    o.y = tf32_rna(vy);
                }
                *(float2*)&Out[idx] = o;
            }
        }
    }
}

// ---------------- s3 tile (device): 32 rows, p3 = s2old @ fw2 ----------------
__device__ __forceinline__ void s3_tile(
    const float* __restrict__ s2old, const float* __restrict__ fw2,
    const float* __restrict__ s3old, const float* __restrict__ y,
    float* __restrict__ s3new, int weak, int rowBase, float* smem)
{
    const int tid = threadIdx.x, lane = tid & 31, wid = tid >> 5;
    float acc[4][NOUT];
#pragma unroll
    for (int r = 0; r < 4; r++)
#pragma unroll
        for (int j = 0; j < NOUT; j++) acc[r][j] = 0.0f;

    float* fs = smem;  // [512][11] padded
    for (int c = 0; c < 8; c++) {
        __syncthreads();
        for (int i = tid; i < 512 * NOUT; i += 256) {
            int kl = i / NOUT, j = i - kl * NOUT;
            fs[kl * 11 + j] = fw2[(size_t)(c * 512 + kl) * NOUT + j];
        }
        __syncthreads();
#pragma unroll
        for (int r = 0; r < 4; r++) {
            const int row = rowBase + wid * 4 + r;
            const float* s2r = s2old + (size_t)row * HID + c * 512;
#pragma unroll 4
            for (int i = 0; i < 16; i++) {
                const int kl = lane + i * 32;
                const float sv = s2r[kl];
#pragma unroll
                for (int j = 0; j < NOUT; j++)
                    acc[r][j] = fmaf(sv, fs[kl * 11 + j], acc[r][j]);
            }
        }
    }

#pragma unroll
    for (int r = 0; r < 4; r++) {
        const int row = rowBase + wid * 4 + r;
#pragma unroll
        for (int j = 0; j < NOUT; j++) {
            float v = acc[r][j];
#pragma unroll
            for (int o = 16; o; o >>= 1) v += __shfl_xor_sync(0xffffffffu, v, o);
            if (lane == 0) {
                float out = weak ? 0.5f * (v + y[row * NOUT + j])
                                 : 0.5f * (s3old[row * NOUT + j] + v);
                s3new[row * NOUT + j] = fminf(fmaxf(out, 0.0f), 1.0f);
            }
        }
    }
}

// ---------------- fused step kernel: 136 CTAs = one wave ----------------
__global__ __launch_bounds__(256, 1) void step_kernel(
    const float* __restrict__ s1old, const float* __restrict__ s2old,
    const float* __restrict__ s3old,
    float* __restrict__ s1new, float* __restrict__ s2new, float* __restrict__ s3new,
    const float* __restrict__ fw1T, const float* __restrict__ bw1T,
    const float* __restrict__ bw2, const float* __restrict__ fw2,
    const float* __restrict__ c0, const float* __restrict__ y, int weak)
{
    extern __shared__ float smem[];
    const int bid = blockIdx.x;
    if (bid < 64) {
        gemm_tile(s2old, bw1T, HID, s1new, s1old, c0, nullptr, nullptr,
                  1, (bid >> 5) * 128, (bid & 31) * 128, smem);
    } else if (bid < 128) {
        const int t = bid - 64;
        gemm_tile(s1old, fw1T, HID, s2new, s2old, nullptr, s3old, bw2,
                  2, (t >> 5) * 128, (t & 31) * 128, smem);
    } else {
        s3_tile(s2old, fw2, s3old, y, s3new, weak, (bid - 128) * 32, smem);
    }
}

__global__ __launch_bounds__(256, 1) void c0_kernel(
    const float* __restrict__ rx, const float* __restrict__ fw0T,
    float* __restrict__ c0)
{
    extern __shared__ float smem[];
    const int bid = blockIdx.x;
    gemm_tile(rx, fw0T, NIN, c0, nullptr, nullptr, nullptr, nullptr,
              0, (bid >> 5) * 128, (bid & 31) * 128, smem);
}

// ---------------- small kernels ----------------
__global__ void clip_kernel(const float* __restrict__ x, float* __restrict__ rx, int n) {
    int i = blockIdx.x * blockDim.x + threadIdx.x;
    if (i < n) rx[i] = tf32_rna(fminf(fmaxf(x[i], 0.0f), 1.0f));
}

__global__ void zero_kernel(float* __restrict__ p, int n) {
    int i = blockIdx.x * blockDim.x + threadIdx.x;
    if (i < n) p[i] = 0.0f;
}

// dst[c,r] = tf32_rna(src[r,c]); src is [R,C], dims multiples of 32
__global__ void transpose_kernel(const float* __restrict__ src, float* __restrict__ dst,
                                 int R, int C) {
    __shared__ float tile[32][33];
    int bx = blockIdx.x * 32, by = blockIdx.y * 32;
    int x = bx + threadIdx.x;
    int y = by + threadIdx.y;
#pragma unroll
    for (int i = 0; i < 32; i += 8)
        tile[threadIdx.y + i][threadIdx.x] = src[(size_t)(y + i) * C + x];
    __syncthreads();
    x = by + threadIdx.x;
    y = bx + threadIdx.y;
#pragma unroll
    for (int i = 0; i < 32; i += 8)
        dst[(size_t)(y + i) * R + x] = tf32_rna(tile[threadIdx.x][threadIdx.y + i]);
}

__global__ void concat_kernel(const float* __restrict__ s1,
                              const float* __restrict__ s2,
                              const float* __restrict__ s3,
                              float* __restrict__ out)
{
    int i = blockIdx.x * blockDim.x + threadIdx.x;
    const int W = HID + HID + NOUT;
    if (i >= BSZ * W) return;
    int row = i / W;
    int c = i - row * W;
    float v;
    if (c < HID)          v = s1[(size_t)row * HID + c];
    else if (c < 2 * HID) v = s2[(size_t)row * HID + (c - HID)];
    else                  v = s3[row * NOUT + (c - 2 * HID)];
    out[i] = v;
}

// ---------------- launch ----------------
extern "C" void kernel_launch(void* const* d_in, const int* in_sizes, int n_in,
                              void* d_out, int out_size)
{
    const float* x   = (const float*)d_in[0];
    const float* fw0 = (const float*)d_in[1];
    const float* fw1 = (const float*)d_in[2];
    const float* fw2 = (const float*)d_in[3];
    // d_in[4] = bw0 (unused by the dynamics)
    const float* bw1 = (const float*)d_in[5];
    const float* bw2 = (const float*)d_in[6];
    const float* y   = (const float*)d_in[7];
    float* out = (float*)d_out;

    cudaFuncSetAttribute(step_kernel, cudaFuncAttributeMaxDynamicSharedMemorySize, SMEM_BYTES);
    cudaFuncSetAttribute(c0_kernel,   cudaFuncAttributeMaxDynamicSharedMemorySize, SMEM_BYTES);

    float *rx, *c0, *s1base, *s2base, *s3base, *fw0T, *fw1T, *bw1T;
    cudaGetSymbolAddress((void**)&rx, g_rx);
    cudaGetSymbolAddress((void**)&c0, g_c0);
    cudaGetSymbolAddress((void**)&s1base, g_s1);
    cudaGetSymbolAddress((void**)&s2base, g_s2);
    cudaGetSymbolAddress((void**)&s3base, g_s3);
    cudaGetSymbolAddress((void**)&fw0T, g_fw0T);
    cudaGetSymbolAddress((void**)&fw1T, g_fw1T);
    cudaGetSymbolAddress((void**)&bw1T, g_bw1T);

    float* s1p[2] = { s1base, s1base + (size_t)BSZ * HID };
    float* s2p[2] = { s2base, s2base + (size_t)BSZ * HID };
    float* s3p[2] = { s3base, s3base + (size_t)BSZ * NOUT };

    // transpose + tf32-round weights (B operands need [N,K])
    {
        dim3 blk(32, 8);
        transpose_kernel<<<dim3(HID / 32, NIN / 32), blk>>>(fw0, fw0T, NIN, HID);
        transpose_kernel<<<dim3(HID / 32, HID / 32), blk>>>(fw1, fw1T, HID, HID);
        transpose_kernel<<<dim3(HID / 32, HID / 32), blk>>>(bw1, bw1T, HID, HID);
    }

    clip_kernel<<<(BSZ * NIN + 255) / 256, 256>>>(x, rx, BSZ * NIN);

    // c0 = rx @ fw0 (loop-invariant)
    c0_kernel<<<64, 256, SMEM_BYTES>>>(rx, fw0T, c0);

    zero_kernel<<<(BSZ * HID + 255) / 256, 256>>>(s1p[0], BSZ * HID);
    zero_kernel<<<(BSZ * HID + 255) / 256, 256>>>(s2p[0], BSZ * HID);
    zero_kernel<<<(BSZ * NOUT + 255) / 256, 256>>>(s3p[0], BSZ * NOUT);

    for (int t = 0; t < STEPS_TOTAL; t++) {
        const int p = t & 1;
        const int q = 1 - p;
        const int weak = (t >= STEPS_FREE) ? 1 : 0;
        step_kernel<<<136, 256, SMEM_BYTES>>>(
            s1p[p], s2p[p], s3p[p],
            s1p[q], s2p[q], s3p[q],
            fw1T, bw1T, bw2, fw2, c0, y, weak);
    }

    const int fin = STEPS_TOTAL & 1;
    concat_kernel<<<(BSZ * (2 * HID + NOUT) + 255) / 256, 256>>>(
        s1p[fin], s2p[fin], s3p[fin], out);
}